// round 2
// baseline (speedup 1.0000x reference)
#include <cuda_runtime.h>
#include <cuda_bf16.h>
#include <cstdint>

#define NMAX   131072      // B*INPUT_LEN
#define ILEN   4096
#define PLEN   1024

// Scratch (__device__ globals; allocation forbidden)
__device__ float  g_deg [NMAX];
__device__ float  g_dinv[NMAX];
__device__ float4 g_hs  [NMAX];   // raw h = x@W1 (k_fused), then h*dinv (k_node)
__device__ float4 g_agg1[NMAX];   // layer1 aggregator
__device__ float  g_t   [NMAX];   // layer2 pre-scaled messages

// ---------------------------------------------------------------------------
// f32x2 helpers (Blackwell packed fp32, PTX-only)
typedef unsigned long long ull;

__device__ __forceinline__ ull fma2(ull a, ull b, ull c) {
    ull d;
    asm("fma.rn.f32x2 %0, %1, %2, %3;" : "=l"(d) : "l"(a), "l"(b), "l"(c));
    return d;
}
__device__ __forceinline__ ull add2(ull a, ull b) {
    ull d;
    asm("add.rn.f32x2 %0, %1, %2;" : "=l"(d) : "l"(a), "l"(b));
    return d;
}
__device__ __forceinline__ ull pack2(float lo, float hi) {
    ull d;
    asm("mov.b64 %0, {%1, %2};" : "=l"(d) : "f"(lo), "f"(hi));
    return d;
}
__device__ __forceinline__ void unpack2(ull v, float& lo, float& hi) {
    asm("mov.b64 {%0, %1}, %2;" : "=f"(lo), "=f"(hi) : "l"(v));
}
__device__ __forceinline__ void red4(float4* p, float a, float b, float c) {
    size_t q = __cvta_generic_to_global(p);
    asm volatile("red.global.add.v4.f32 [%0], {%1, %2, %3, %4};"
                 :: "l"(q), "f"(a), "f"(b), "f"(c), "f"(0.0f) : "memory");
}

// ---------------------------------------------------------------------------
// K1: deg = 1 (self loop)
__global__ void k_init_deg(int N) {
    int i = blockIdx.x * blockDim.x + threadIdx.x;
    if (i < N) g_deg[i] = 1.0f;
}

// K2 (fused): blocks [0, DEG_B) accumulate degree; blocks [DEG_B, ...) compute
// raw h = x@W1 into g_hs. The two halves are independent and overlap.
#define DEG_B 384
__global__ __launch_bounds__(256)
void k_fused(const longlong2* __restrict__ Xll,
             const float* __restrict__ W1,
             const int* __restrict__ dst, int N, int E) {
    if (blockIdx.x < DEG_B) {
        // ---- degree path ----
        int stride = DEG_B * blockDim.x;
        int i = blockIdx.x * blockDim.x + threadIdx.x;
        int E4 = E >> 2;
        const int4* dst4 = (const int4*)dst;
        for (int e = i; e < E4; e += stride) {
            int4 d = dst4[e];
            atomicAdd(&g_deg[d.x], 1.0f);
            atomicAdd(&g_deg[d.y], 1.0f);
            atomicAdd(&g_deg[d.z], 1.0f);
            atomicAdd(&g_deg[d.w], 1.0f);
        }
        for (int e = (E4 << 2) + i; e < E; e += stride)
            atomicAdd(&g_deg[dst[e]], 1.0f);
        return;
    }
    // ---- linear path: 16 lanes per node, 4 nodes per warp iteration ----
    int lane = threadIdx.x & 31;
    int sub  = lane & 15;          // lane within 16-lane subgroup
    int half = lane >> 4;          // 0 or 1: selects node parity
    int warp = (((blockIdx.x - DEG_B) * blockDim.x) + threadIdx.x) >> 5;
    int nwarps = ((gridDim.x - DEG_B) * blockDim.x) >> 5;

    // Preload packed weights: lane owns chunks c = sub + 16j (j=0..3),
    // each chunk = features 4c..4c+3.  wp[j][k][p] = (w[4c+2p][k], w[4c+2p+1][k])
    ull wp[4][3][2];
#pragma unroll
    for (int j = 0; j < 4; j++) {
        int c = sub + 16 * j;
#pragma unroll
        for (int k = 0; k < 3; k++) {
            wp[j][k][0] = pack2(W1[(4 * c + 0) * 3 + k], W1[(4 * c + 1) * 3 + k]);
            wp[j][k][1] = pack2(W1[(4 * c + 2) * 3 + k], W1[(4 * c + 3) * 3 + k]);
        }
    }

    int NG = N >> 2;   // groups of 4 nodes
    for (int g = warp; g < NG; g += nwarps) {
        int nA = 4 * g + half;       // pair 0
        int nB = nA + 2;             // pair 1
        // Issue all 8 loads up front (independent, 128-bit each)
        longlong2 va[4], vb[4];
        size_t baseA = (size_t)nA * 64 + sub;
        size_t baseB = (size_t)nB * 64 + sub;
#pragma unroll
        for (int j = 0; j < 4; j++) va[j] = Xll[baseA + 16 * j];
#pragma unroll
        for (int j = 0; j < 4; j++) vb[j] = Xll[baseB + 16 * j];

        ull aA0 = 0, aA1 = 0, aA2 = 0, aB0 = 0, aB1 = 0, aB2 = 0;
#pragma unroll
        for (int j = 0; j < 4; j++) {
            ull alo = (ull)va[j].x, ahi = (ull)va[j].y;
            ull blo = (ull)vb[j].x, bhi = (ull)vb[j].y;
            aA0 = fma2(alo, wp[j][0][0], aA0);  aA0 = fma2(ahi, wp[j][0][1], aA0);
            aA1 = fma2(alo, wp[j][1][0], aA1);  aA1 = fma2(ahi, wp[j][1][1], aA1);
            aA2 = fma2(alo, wp[j][2][0], aA2);  aA2 = fma2(ahi, wp[j][2][1], aA2);
            aB0 = fma2(blo, wp[j][0][0], aB0);  aB0 = fma2(bhi, wp[j][0][1], aB0);
            aB1 = fma2(blo, wp[j][1][0], aB1);  aB1 = fma2(bhi, wp[j][1][1], aB1);
            aB2 = fma2(blo, wp[j][2][0], aB2);  aB2 = fma2(bhi, wp[j][2][1], aB2);
        }
        // Collapse pairs: keep (h0,h1) packed, h2 scalar, per node.
        float t0, t1;
        unpack2(aA0, t0, t1); float hA0 = t0 + t1;
        unpack2(aA1, t0, t1); float hA1 = t0 + t1;
        unpack2(aA2, t0, t1); float hA2 = t0 + t1;
        unpack2(aB0, t0, t1); float hB0 = t0 + t1;
        unpack2(aB1, t0, t1); float hB1 = t0 + t1;
        unpack2(aB2, t0, t1); float hB2 = t0 + t1;
        ull pA = pack2(hA0, hA1);
        ull pB = pack2(hB0, hB1);
        // 4-round tree over 16 lanes; two independent chains interleaved
#pragma unroll
        for (int off = 8; off; off >>= 1) {
            ull qA = __shfl_xor_sync(0xffffffffu, pA, off);
            ull qB = __shfl_xor_sync(0xffffffffu, pB, off);
            float rA = __shfl_xor_sync(0xffffffffu, hA2, off);
            float rB = __shfl_xor_sync(0xffffffffu, hB2, off);
            pA = add2(pA, qA);
            pB = add2(pB, qB);
            hA2 += rA;
            hB2 += rB;
        }
        if (sub == 0) {
            float x0, x1;
            unpack2(pA, x0, x1);
            g_hs[nA] = make_float4(x0, x1, hA2, 0.0f);
            unpack2(pB, x0, x1);
            g_hs[nB] = make_float4(x0, x1, hB2, 0.0f);
        }
    }
}

// K3: node pass — dinv = rsqrt(deg); hs = h*dinv; agg1 = h*dinv^2 (self loop)
__global__ void k_node(int N) {
    int n = blockIdx.x * blockDim.x + threadIdx.x;
    if (n >= N) return;
    float dv = rsqrtf(g_deg[n]);
    g_dinv[n] = dv;
    float4 h = g_hs[n];
    float4 hs = make_float4(h.x * dv, h.y * dv, h.z * dv, 0.0f);
    g_hs[n] = hs;
    g_agg1[n] = make_float4(hs.x * dv, hs.y * dv, hs.z * dv, 0.0f);
}

// K4: layer-1 scatter (4 edges/thread): agg1[dst] += hs[src] * dinv[dst]
__global__ void k_edge1(const int* __restrict__ ei, int E) {
    int stride = gridDim.x * blockDim.x;
    int i = blockIdx.x * blockDim.x + threadIdx.x;
    int E4 = E >> 2;
    const int4* s4 = (const int4*)ei;
    const int4* d4 = (const int4*)(ei + E);
    for (int e = i; e < E4; e += stride) {
        int4 s = s4[e];
        int4 d = d4[e];
        float4 h0 = g_hs[s.x];
        float4 h1 = g_hs[s.y];
        float4 h2 = g_hs[s.z];
        float4 h3 = g_hs[s.w];
        float n0 = g_dinv[d.x];
        float n1 = g_dinv[d.y];
        float n2 = g_dinv[d.z];
        float n3 = g_dinv[d.w];
        red4(&g_agg1[d.x], h0.x * n0, h0.y * n0, h0.z * n0);
        red4(&g_agg1[d.y], h1.x * n1, h1.y * n1, h1.z * n1);
        red4(&g_agg1[d.z], h2.x * n2, h2.y * n2, h2.z * n2);
        red4(&g_agg1[d.w], h3.x * n3, h3.y * n3, h3.z * n3);
    }
    for (int e = (E4 << 2) + i; e < E; e += stride) {
        int s = ei[e], d = ei[E + e];
        float4 h = g_hs[s];
        float nd = g_dinv[d];
        red4(&g_agg1[d], h.x * nd, h.y * nd, h.z * nd);
    }
}

// K5: finalize layer1 (relu(+b1)), apply W2, pre-scale t = h2*dinv,
//     seed d_out with self-loop term + b2 for output-window nodes.
__global__ void k_final1(const float* __restrict__ b1,
                         const float* __restrict__ W2,
                         const float* __restrict__ b2,
                         float* __restrict__ out, int N) {
    int n = blockIdx.x * blockDim.x + threadIdx.x;
    if (n >= N) return;
    float4 a = g_agg1[n];
    float o0 = fmaxf(a.x + b1[0], 0.0f);
    float o1 = fmaxf(a.y + b1[1], 0.0f);
    float o2 = fmaxf(a.z + b1[2], 0.0f);
    float h2 = o0 * W2[0] + o1 * W2[1] + o2 * W2[2];
    float dv = g_dinv[n];
    g_t[n] = h2 * dv;
    int r = n & (ILEN - 1);
    if (r < PLEN)
        out[(n >> 12) * PLEN + r] = h2 * dv * dv + b2[0];
}

// K6: layer-2 scatter, filtered to output-window destinations (4 edges/thread)
__global__ void k_edge2(const int* __restrict__ ei, float* __restrict__ out,
                        int E) {
    int stride = gridDim.x * blockDim.x;
    int i = blockIdx.x * blockDim.x + threadIdx.x;
    int E4 = E >> 2;
    const int4* s4 = (const int4*)ei;
    const int4* d4 = (const int4*)(ei + E);
    for (int e = i; e < E4; e += stride) {
        int4 d = d4[e];
        int4 s = s4[e];
        int r0 = d.x & (ILEN - 1);
        int r1 = d.y & (ILEN - 1);
        int r2 = d.z & (ILEN - 1);
        int r3 = d.w & (ILEN - 1);
        if (r0 < PLEN) atomicAdd(&out[(d.x >> 12) * PLEN + r0], g_t[s.x] * g_dinv[d.x]);
        if (r1 < PLEN) atomicAdd(&out[(d.y >> 12) * PLEN + r1], g_t[s.y] * g_dinv[d.y]);
        if (r2 < PLEN) atomicAdd(&out[(d.z >> 12) * PLEN + r2], g_t[s.z] * g_dinv[d.z]);
        if (r3 < PLEN) atomicAdd(&out[(d.w >> 12) * PLEN + r3], g_t[s.w] * g_dinv[d.w]);
    }
    for (int e = (E4 << 2) + i; e < E; e += stride) {
        int d = ei[E + e];
        int r = d & (ILEN - 1);
        if (r < PLEN) {
            int s = ei[e];
            atomicAdd(&out[(d >> 12) * PLEN + r], g_t[s] * g_dinv[d]);
        }
    }
}

// ---------------------------------------------------------------------------
extern "C" void kernel_launch(void* const* d_in, const int* in_sizes, int n_in,
                              void* d_out, int out_size) {
    const float* X   = (const float*)d_in[0];   // [N,256]
    const float* W1  = (const float*)d_in[1];   // [256,3]
    const float* b1  = (const float*)d_in[2];   // [3]
    const float* W2  = (const float*)d_in[3];   // [3,1]
    const float* b2  = (const float*)d_in[4];   // [1]
    const int*   ei  = (const int*)d_in[5];     // [2,E]
    float*       out = (float*)d_out;

    int N = in_sizes[0] / 256;
    int E = in_sizes[5] / 2;

    const int T = 256;
    int nb_node = (N + T - 1) / T;

    k_init_deg<<<nb_node, T>>>(N);
    k_fused<<<DEG_B + 768, T>>>((const longlong2*)X, W1, ei + E, N, E);
    k_node<<<nb_node, T>>>(N);
    k_edge1<<<2048, T>>>(ei, E);
    k_final1<<<nb_node, T>>>(b1, W2, b2, out, N);
    k_edge2<<<2048, T>>>(ei, out, E);
}

// round 3
// speedup vs baseline: 1.1747x; 1.1747x over previous
#include <cuda_runtime.h>
#include <cuda_bf16.h>
#include <cstdint>

#define NMAX   131072      // B*INPUT_LEN
#define ILEN   4096
#define PLEN   1024
#define WTOT   (NMAX / ILEN * PLEN)   // 32768 output elements

// Scratch (__device__ globals; allocation forbidden)
__device__ float  g_deg [NMAX];
__device__ float  g_dinv[NMAX];
__device__ float4 g_hs  [NMAX];   // raw h = x@W1, then h*dinv after k_node
__device__ float4 g_agg1[NMAX];   // layer1 unnormalized aggregator
__device__ float  g_t   [NMAX];   // layer2 pre-scaled messages t = h2*dinv
__device__ float  g_u   [WTOT];   // layer2 window accumulator (unnormalized)

// ---------------------------------------------------------------------------
typedef unsigned long long ull;

__device__ __forceinline__ ull fma2(ull a, ull b, ull c) {
    ull d;
    asm("fma.rn.f32x2 %0, %1, %2, %3;" : "=l"(d) : "l"(a), "l"(b), "l"(c));
    return d;
}
__device__ __forceinline__ ull add2(ull a, ull b) {
    ull d;
    asm("add.rn.f32x2 %0, %1, %2;" : "=l"(d) : "l"(a), "l"(b));
    return d;
}
__device__ __forceinline__ ull pack2(float lo, float hi) {
    ull d;
    asm("mov.b64 %0, {%1, %2};" : "=l"(d) : "f"(lo), "f"(hi));
    return d;
}
__device__ __forceinline__ void unpack2(ull v, float& lo, float& hi) {
    asm("mov.b64 {%0, %1}, %2;" : "=f"(lo), "=f"(hi) : "l"(v));
}
__device__ __forceinline__ void red4(float4* p, float a, float b, float c) {
    size_t q = __cvta_generic_to_global(p);
    asm volatile("red.global.add.v4.f32 [%0], {%1, %2, %3, %4};"
                 :: "l"(q), "f"(a), "f"(b), "f"(c), "f"(0.0f) : "memory");
}

// ---------------------------------------------------------------------------
// K1: deg = 1 (self loop)
__global__ void k_init_deg(int N) {
    int i = blockIdx.x * blockDim.x + threadIdx.x;
    if (i < N) g_deg[i] = 1.0f;
}

// K2 (fused): blocks [0, DEG_B): degree histogram; rest: raw h = x@W1.
#define DEG_B 384
__global__ __launch_bounds__(256)
void k_fused(const longlong2* __restrict__ Xll,
             const float* __restrict__ W1,
             const int* __restrict__ dst, int N, int E) {
    if (blockIdx.x < DEG_B) {
        int stride = DEG_B * blockDim.x;
        int i = blockIdx.x * blockDim.x + threadIdx.x;
        int E4 = E >> 2;
        const int4* dst4 = (const int4*)dst;
        for (int e = i; e < E4; e += stride) {
            int4 d = dst4[e];
            atomicAdd(&g_deg[d.x], 1.0f);
            atomicAdd(&g_deg[d.y], 1.0f);
            atomicAdd(&g_deg[d.z], 1.0f);
            atomicAdd(&g_deg[d.w], 1.0f);
        }
        for (int e = (E4 << 2) + i; e < E; e += stride)
            atomicAdd(&g_deg[dst[e]], 1.0f);
        return;
    }
    // linear path: 16 lanes per node, 4 nodes per warp iteration
    int lane = threadIdx.x & 31;
    int sub  = lane & 15;
    int half = lane >> 4;
    int warp = (((blockIdx.x - DEG_B) * blockDim.x) + threadIdx.x) >> 5;
    int nwarps = ((gridDim.x - DEG_B) * blockDim.x) >> 5;

    ull wp[4][3][2];
#pragma unroll
    for (int j = 0; j < 4; j++) {
        int c = sub + 16 * j;
#pragma unroll
        for (int k = 0; k < 3; k++) {
            wp[j][k][0] = pack2(W1[(4 * c + 0) * 3 + k], W1[(4 * c + 1) * 3 + k]);
            wp[j][k][1] = pack2(W1[(4 * c + 2) * 3 + k], W1[(4 * c + 3) * 3 + k]);
        }
    }

    int NG = N >> 2;
    for (int g = warp; g < NG; g += nwarps) {
        int nA = 4 * g + half;
        int nB = nA + 2;
        longlong2 va[4], vb[4];
        size_t baseA = (size_t)nA * 64 + sub;
        size_t baseB = (size_t)nB * 64 + sub;
#pragma unroll
        for (int j = 0; j < 4; j++) va[j] = Xll[baseA + 16 * j];
#pragma unroll
        for (int j = 0; j < 4; j++) vb[j] = Xll[baseB + 16 * j];

        ull aA0 = 0, aA1 = 0, aA2 = 0, aB0 = 0, aB1 = 0, aB2 = 0;
#pragma unroll
        for (int j = 0; j < 4; j++) {
            ull alo = (ull)va[j].x, ahi = (ull)va[j].y;
            ull blo = (ull)vb[j].x, bhi = (ull)vb[j].y;
            aA0 = fma2(alo, wp[j][0][0], aA0);  aA0 = fma2(ahi, wp[j][0][1], aA0);
            aA1 = fma2(alo, wp[j][1][0], aA1);  aA1 = fma2(ahi, wp[j][1][1], aA1);
            aA2 = fma2(alo, wp[j][2][0], aA2);  aA2 = fma2(ahi, wp[j][2][1], aA2);
            aB0 = fma2(blo, wp[j][0][0], aB0);  aB0 = fma2(bhi, wp[j][0][1], aB0);
            aB1 = fma2(blo, wp[j][1][0], aB1);  aB1 = fma2(bhi, wp[j][1][1], aB1);
            aB2 = fma2(blo, wp[j][2][0], aB2);  aB2 = fma2(bhi, wp[j][2][1], aB2);
        }
        float t0, t1;
        unpack2(aA0, t0, t1); float hA0 = t0 + t1;
        unpack2(aA1, t0, t1); float hA1 = t0 + t1;
        unpack2(aA2, t0, t1); float hA2 = t0 + t1;
        unpack2(aB0, t0, t1); float hB0 = t0 + t1;
        unpack2(aB1, t0, t1); float hB1 = t0 + t1;
        unpack2(aB2, t0, t1); float hB2 = t0 + t1;
        ull pA = pack2(hA0, hA1);
        ull pB = pack2(hB0, hB1);
#pragma unroll
        for (int off = 8; off; off >>= 1) {
            ull qA = __shfl_xor_sync(0xffffffffu, pA, off);
            ull qB = __shfl_xor_sync(0xffffffffu, pB, off);
            float rA = __shfl_xor_sync(0xffffffffu, hA2, off);
            float rB = __shfl_xor_sync(0xffffffffu, hB2, off);
            pA = add2(pA, qA);
            pB = add2(pB, qB);
            hA2 += rA;
            hB2 += rB;
        }
        if (sub == 0) {
            float x0, x1;
            unpack2(pA, x0, x1);
            g_hs[nA] = make_float4(x0, x1, hA2, 0.0f);
            unpack2(pB, x0, x1);
            g_hs[nB] = make_float4(x0, x1, hB2, 0.0f);
        }
    }
}

// K3: node pass — dinv = rsqrt(deg); hs = h*dinv; agg1 = hs (self loop,
// destination dinv deferred to k_final1)
__global__ void k_node(int N) {
    int n = blockIdx.x * blockDim.x + threadIdx.x;
    if (n >= N) return;
    float dv = rsqrtf(g_deg[n]);
    g_dinv[n] = dv;
    float4 h = g_hs[n];
    float4 hs = make_float4(h.x * dv, h.y * dv, h.z * dv, 0.0f);
    g_hs[n] = hs;
    g_agg1[n] = hs;            // self-loop contribution, unnormalized
}

// K4: layer-1 scatter: agg1[d] += hs[s]   (no dinv gather — deferred)
__global__ void k_edge1(const int* __restrict__ ei, int E) {
    int stride = gridDim.x * blockDim.x;
    int i = blockIdx.x * blockDim.x + threadIdx.x;
    int E4 = E >> 2;
    const int4* s4 = (const int4*)ei;
    const int4* d4 = (const int4*)(ei + E);
    for (int e = i; e < E4; e += stride) {
        int4 s = s4[e];
        int4 d = d4[e];
        float4 h0 = g_hs[s.x];
        float4 h1 = g_hs[s.y];
        float4 h2 = g_hs[s.z];
        float4 h3 = g_hs[s.w];
        red4(&g_agg1[d.x], h0.x, h0.y, h0.z);
        red4(&g_agg1[d.y], h1.x, h1.y, h1.z);
        red4(&g_agg1[d.z], h2.x, h2.y, h2.z);
        red4(&g_agg1[d.w], h3.x, h3.y, h3.z);
    }
    for (int e = (E4 << 2) + i; e < E; e += stride) {
        int s = ei[e], d = ei[E + e];
        float4 h = g_hs[s];
        red4(&g_agg1[d], h.x, h.y, h.z);
    }
}

// K5: finalize layer1: a = agg1*dinv (+b1, relu) -> h2 -> t = h2*dinv.
//     Seed window accumulator g_u with self-loop term t[n].
__global__ void k_final1(const float* __restrict__ b1,
                         const float* __restrict__ W2, int N) {
    int n = blockIdx.x * blockDim.x + threadIdx.x;
    if (n >= N) return;
    float dv = g_dinv[n];
    float4 a = g_agg1[n];
    float o0 = fmaxf(a.x * dv + b1[0], 0.0f);
    float o1 = fmaxf(a.y * dv + b1[1], 0.0f);
    float o2 = fmaxf(a.z * dv + b1[2], 0.0f);
    float h2 = o0 * W2[0] + o1 * W2[1] + o2 * W2[2];
    float t = h2 * dv;
    g_t[n] = t;
    int r = n & (ILEN - 1);
    if (r < PLEN)
        g_u[(n >> 12) * PLEN + r] = t;   // self loop contribution
}

// K6: layer-2 scatter, filtered, unnormalized: u[d] += t[s]
__global__ void k_edge2(const int* __restrict__ ei, int E) {
    int stride = gridDim.x * blockDim.x;
    int i = blockIdx.x * blockDim.x + threadIdx.x;
    int E4 = E >> 2;
    const int4* s4 = (const int4*)ei;
    const int4* d4 = (const int4*)(ei + E);
    for (int e = i; e < E4; e += stride) {
        int4 d = d4[e];
        int4 s = s4[e];
        int r0 = d.x & (ILEN - 1);
        int r1 = d.y & (ILEN - 1);
        int r2 = d.z & (ILEN - 1);
        int r3 = d.w & (ILEN - 1);
        if (r0 < PLEN) atomicAdd(&g_u[(d.x >> 12) * PLEN + r0], g_t[s.x]);
        if (r1 < PLEN) atomicAdd(&g_u[(d.y >> 12) * PLEN + r1], g_t[s.y]);
        if (r2 < PLEN) atomicAdd(&g_u[(d.z >> 12) * PLEN + r2], g_t[s.z]);
        if (r3 < PLEN) atomicAdd(&g_u[(d.w >> 12) * PLEN + r3], g_t[s.w]);
    }
    for (int e = (E4 << 2) + i; e < E; e += stride) {
        int d = ei[E + e];
        int r = d & (ILEN - 1);
        if (r < PLEN)
            atomicAdd(&g_u[(d >> 12) * PLEN + r], g_t[ei[e]]);
    }
}

// K7: final output: out = u * dinv[node] + b2
__global__ void k_out(const float* __restrict__ b2, float* __restrict__ out) {
    int i = blockIdx.x * blockDim.x + threadIdx.x;
    if (i >= WTOT) return;
    int n = (i >> 10) * ILEN + (i & (PLEN - 1));
    out[i] = g_u[i] * g_dinv[n] + b2[0];
}

// ---------------------------------------------------------------------------
extern "C" void kernel_launch(void* const* d_in, const int* in_sizes, int n_in,
                              void* d_out, int out_size) {
    const float* X   = (const float*)d_in[0];   // [N,256]
    const float* W1  = (const float*)d_in[1];   // [256,3]
    const float* b1  = (const float*)d_in[2];   // [3]
    const float* W2  = (const float*)d_in[3];   // [3,1]
    const float* b2  = (const float*)d_in[4];   // [1]
    const int*   ei  = (const int*)d_in[5];     // [2,E]
    float*       out = (float*)d_out;

    int N = in_sizes[0] / 256;
    int E = in_sizes[5] / 2;

    const int T = 256;
    int nb_node = (N + T - 1) / T;

    k_init_deg<<<nb_node, T>>>(N);
    k_fused<<<DEG_B + 768, T>>>((const longlong2*)X, W1, ei + E, N, E);
    k_node<<<nb_node, T>>>(N);
    k_edge1<<<4096, T>>>(ei, E);
    k_final1<<<nb_node, T>>>(b1, W2, N);
    k_edge2<<<4096, T>>>(ei, E);
    k_out<<<(WTOT + T - 1) / T, T>>>(b2, out);
}